// round 5
// baseline (speedup 1.0000x reference)
#include <cuda_runtime.h>
#include <cuda_bf16.h>
#include <math.h>

// ---------------------------------------------------------------------------
// Problem constants
// ---------------------------------------------------------------------------
#define BB   2
#define LQ   12240
#define DMO  256
#define MH   8
#define LL   4
#define PP   4
#define DD   32            // DMO / MH
#define ROWS (BB * LQ)     // 24480

// Level geometry (hardcoded from SHAPES = [(96,96),(48,48),(24,24),(12,12)])
__device__ __constant__ int   c_H[4]  = {96, 48, 24, 12};
__device__ __constant__ int   c_W[4]  = {96, 48, 24, 12};
__device__ __constant__ int   c_ST[4] = {0, 9216, 11520, 12096};

// ---------------------------------------------------------------------------
// Scratch (static device globals: allocation-free, graph-safe)
// ---------------------------------------------------------------------------
__device__ float g_value[ROWS * DMO];   // input_flatten @ Wv + bv
__device__ float g_offs [ROWS * DMO];   // query @ Ws + bs   (M*L*P*2 = 256)
__device__ float g_alog [ROWS * 128];   // query @ Wa + ba   (M*L*P = 128)
__device__ float g_msout[ROWS * DMO];   // deformable-attention output

// ---------------------------------------------------------------------------
// Tiled SGEMM + bias:  C[rows x ncols] = A[rows x 256] * W[256 x ncols] + b
// BM=64, BN=64, BK=16, 256 threads, 4x4 register tile per thread.
// ncols must be a multiple of 64 (it is: 256 / 128). rows is guarded.
// ---------------------------------------------------------------------------
__global__ void __launch_bounds__(256)
sgemm_bias(const float* __restrict__ A, const float* __restrict__ Wm,
           const float* __restrict__ bias, float* __restrict__ C,
           int rows, int ncols)
{
    __shared__ float As[16][64];
    __shared__ float Bs[16][64];

    const int tid = threadIdx.x;
    const int tx  = tid & 15;        // output col group
    const int ty  = tid >> 4;        // output row group
    const int rowBase = blockIdx.x * 64;
    const int colBase = blockIdx.y * 64;

    // A-tile load mapping: float4 per thread
    const int arow = tid >> 2;           // 0..63
    const int ak   = (tid & 3) * 4;      // 0,4,8,12
    // B-tile load mapping: float4 per thread
    const int bk   = tid >> 4;           // 0..15
    const int bcol = (tid & 15) * 4;     // 0..60

    const int  grow  = rowBase + arow;
    const bool rowOk = (grow < rows);
    const float* Aptr = A + (size_t)grow * 256;

    float acc[4][4] = {};

    for (int kb = 0; kb < 256; kb += 16) {
        float4 av = rowOk ? *(const float4*)(Aptr + kb + ak)
                          : make_float4(0.f, 0.f, 0.f, 0.f);
        float4 bvv = *(const float4*)(Wm + (size_t)(kb + bk) * ncols + colBase + bcol);

        As[ak + 0][arow] = av.x;
        As[ak + 1][arow] = av.y;
        As[ak + 2][arow] = av.z;
        As[ak + 3][arow] = av.w;
        *(float4*)&Bs[bk][bcol] = bvv;
        __syncthreads();

        #pragma unroll
        for (int k = 0; k < 16; k++) {
            float4 a4 = *(const float4*)&As[k][ty * 4];
            float4 b4 = *(const float4*)&Bs[k][tx * 4];
            float ar[4] = {a4.x, a4.y, a4.z, a4.w};
            float br[4] = {b4.x, b4.y, b4.z, b4.w};
            #pragma unroll
            for (int i = 0; i < 4; i++)
                #pragma unroll
                for (int j = 0; j < 4; j++)
                    acc[i][j] = fmaf(ar[i], br[j], acc[i][j]);
        }
        __syncthreads();
    }

    // Epilogue: +bias, vectorized store
    float4 bvec = *(const float4*)(bias + colBase + tx * 4);
    #pragma unroll
    for (int i = 0; i < 4; i++) {
        int r = rowBase + ty * 4 + i;
        if (r < rows) {
            float4 o;
            o.x = acc[i][0] + bvec.x;
            o.y = acc[i][1] + bvec.y;
            o.z = acc[i][2] + bvec.z;
            o.w = acc[i][3] + bvec.w;
            *(float4*)(C + (size_t)r * ncols + colBase + tx * 4) = o;
        }
    }
}

// ---------------------------------------------------------------------------
// Fused softmax + deformable bilinear sampling.
// One warp per (b*LQ+lq, m). lane = channel d (0..31) -> each corner gather is
// one coalesced 128B vector from g_value.
// ---------------------------------------------------------------------------
__global__ void __launch_bounds__(256)
sample_kernel(const float* __restrict__ value,
              const float* __restrict__ offs,
              const float* __restrict__ alog,
              const float* __restrict__ refp,
              float* __restrict__ msout)
{
    const int gwarp = (blockIdx.x * blockDim.x + threadIdx.x) >> 5;
    const int lane  = threadIdx.x & 31;
    if (gwarp >= ROWS * MH) return;

    const int m   = gwarp & (MH - 1);   // head (fastest so a block shares a row)
    const int row = gwarp >> 3;         // b*LQ + lq
    const int b   = (row >= LQ) ? 1 : 0;

    // ---- softmax over the 16 (l,p) logits, via warp shuffles ----
    const float* lg = alog + (size_t)row * 128 + m * 16;
    float v = (lane < 16) ? lg[lane] : -1e30f;
    float mx = v;
    #pragma unroll
    for (int o = 16; o; o >>= 1) mx = fmaxf(mx, __shfl_xor_sync(0xffffffffu, mx, o));
    float e = (lane < 16) ? expf(v - mx) : 0.f;
    float s = e;
    #pragma unroll
    for (int o = 16; o; o >>= 1) s += __shfl_xor_sync(0xffffffffu, s, o);
    const float inv = 1.f / s;

    const float* od    = offs + (size_t)row * 256 + m * 32;
    const float* vbase = value + (size_t)b * LQ * 256 + m * 32 + lane;

    float acc = 0.f;

    #pragma unroll
    for (int l = 0; l < LL; l++) {
        const int H  = c_H[l];
        const int W  = c_W[l];
        const int st = c_ST[l];
        const float rx = refp[(row * 4 + l) * 2 + 0];
        const float ry = refp[(row * 4 + l) * 2 + 1];
        const float fW = (float)W, fH = (float)H;

        #pragma unroll
        for (int p = 0; p < PP; p++) {
            const float ox = od[l * 8 + p * 2 + 0];
            const float oy = od[l * 8 + p * 2 + 1];
            // locs = ref + offs / norm ; norm = (W, H)
            const float lx = rx + ox / fW;
            const float ly = ry + oy / fH;
            // g = 2*loc - 1 ; x = ((g+1)*W - 1) * 0.5  (match ref op order)
            const float gx = 2.f * lx - 1.f;
            const float gy = 2.f * ly - 1.f;
            const float x  = ((gx + 1.f) * fW - 1.f) * 0.5f;
            const float y  = ((gy + 1.f) * fH - 1.f) * 0.5f;

            const float x0 = floorf(x), y0 = floorf(y);
            const float fx = x - x0,    fy = y - y0;
            const int ix = (int)x0, iy = (int)y0;

            const float w00 = (1.f - fx) * (1.f - fy);
            const float w01 = fx * (1.f - fy);
            const float w10 = (1.f - fx) * fy;
            const float w11 = fx * fy;

            const bool vx0 = (ix >= 0)     && (ix < W);
            const bool vx1 = (ix + 1 >= 0) && (ix + 1 < W);
            const bool vy0 = (iy >= 0)     && (iy < H);
            const bool vy1 = (iy + 1 >= 0) && (iy + 1 < H);

            const int cx0 = min(max(ix, 0), W - 1);
            const int cx1 = min(max(ix + 1, 0), W - 1);
            const int cy0 = min(max(iy, 0), H - 1);
            const int cy1 = min(max(iy + 1, 0), H - 1);

            float samp = 0.f;
            if (vx0 && vy0) samp = fmaf(w00, vbase[(st + cy0 * W + cx0) * 256], samp);
            if (vx1 && vy0) samp = fmaf(w01, vbase[(st + cy0 * W + cx1) * 256], samp);
            if (vx0 && vy1) samp = fmaf(w10, vbase[(st + cy1 * W + cx0) * 256], samp);
            if (vx1 && vy1) samp = fmaf(w11, vbase[(st + cy1 * W + cx1) * 256], samp);

            const float lw = __shfl_sync(0xffffffffu, e, l * 4 + p) * inv;
            acc = fmaf(lw, samp, acc);
        }
    }

    msout[(size_t)row * 256 + m * 32 + lane] = acc;
}

// ---------------------------------------------------------------------------
// Launch: 5 graph-capturable kernel launches on the default stream.
// ---------------------------------------------------------------------------
extern "C" void kernel_launch(void* const* d_in, const int* in_sizes, int n_in,
                              void* d_out, int out_size)
{
    (void)in_sizes; (void)n_in; (void)out_size;

    const float* query = (const float*)d_in[0];
    const float* refp  = (const float*)d_in[1];
    const float* inpf  = (const float*)d_in[2];
    // d_in[3] = spatial_shapes (hardcoded)
    const float* Wv = (const float*)d_in[4];
    const float* bv = (const float*)d_in[5];
    const float* Ws = (const float*)d_in[6];
    const float* bs = (const float*)d_in[7];
    const float* Wa = (const float*)d_in[8];
    const float* ba = (const float*)d_in[9];
    const float* Wo = (const float*)d_in[10];
    const float* bo = (const float*)d_in[11];
    float* out = (float*)d_out;

    float *value, *offs, *alog, *msout;
    cudaGetSymbolAddress((void**)&value, g_value);
    cudaGetSymbolAddress((void**)&offs,  g_offs);
    cudaGetSymbolAddress((void**)&alog,  g_alog);
    cudaGetSymbolAddress((void**)&msout, g_msout);

    const dim3 blk(256);
    const dim3 g256((ROWS + 63) / 64, 4);   // N = 256
    const dim3 g128((ROWS + 63) / 64, 2);   // N = 128

    // 1) value = input_flatten @ Wv + bv
    sgemm_bias<<<g256, blk>>>(inpf, Wv, bv, value, ROWS, 256);
    // 2) sampling offsets = query @ Ws + bs
    sgemm_bias<<<g256, blk>>>(query, Ws, bs, offs, ROWS, 256);
    // 3) attention logits = query @ Wa + ba
    sgemm_bias<<<g128, blk>>>(query, Wa, ba, alog, ROWS, 128);
    // 4) fused softmax + deformable bilinear sampling
    sample_kernel<<<ROWS * MH / 8, blk>>>(value, offs, alog, refp, msout);
    // 5) out = msout @ Wo + bo
    sgemm_bias<<<g256, blk>>>(msout, Wo, bo, out, ROWS, 256);
}

// round 6
// speedup vs baseline: 1.3218x; 1.3218x over previous
#include <cuda_runtime.h>
#include <cuda_bf16.h>
#include <math.h>
#include <stdint.h>

// ---------------------------------------------------------------------------
// Problem constants
// ---------------------------------------------------------------------------
#define BB   2
#define LQ   12240
#define DMO  256
#define MH   8
#define LL   4
#define PP   4
#define ROWS (BB * LQ)     // 24480

// Level geometry (hardcoded from SHAPES = [(96,96),(48,48),(24,24),(12,12)])
__device__ __constant__ int c_H[4]  = {96, 48, 24, 12};
__device__ __constant__ int c_W[4]  = {96, 48, 24, 12};
__device__ __constant__ int c_ST[4] = {0, 9216, 11520, 12096};

// ---------------------------------------------------------------------------
// Scratch (static device globals: allocation-free, graph-safe)
// ---------------------------------------------------------------------------
__device__ float g_value[ROWS * DMO];
__device__ float g_offs [ROWS * DMO];
__device__ float g_alog [ROWS * 128];
__device__ float g_msout[ROWS * DMO];

// ---------------------------------------------------------------------------
// Packed f32x2 helpers (Blackwell sm_100a: 2 fp32 FMAs per issue slot)
// ---------------------------------------------------------------------------
__device__ __forceinline__ unsigned long long pack2(float lo, float hi) {
    unsigned long long r;
    asm("mov.b64 %0, {%1, %2};" : "=l"(r) : "f"(lo), "f"(hi));
    return r;
}
#define FMA2(d, a, b) \
    asm("fma.rn.f32x2 %0, %1, %2, %0;" : "+l"(d) : "l"(a), "l"(b))

// ---------------------------------------------------------------------------
// SGEMM + bias with packed f32x2 FMAs.
// C[rows x ncols] = A[rows x 256] * W[256 x ncols] + bias
// BM=128, BN=128, BK=16, 256 threads, 8x8 per thread (32 packed accumulators).
// A is staged in smem as duplicated (a,a) 64-bit pairs so the inner loop is
// pure LDS.128 + fma.f32x2 (no repacking MOVs).
// ---------------------------------------------------------------------------
__global__ void __launch_bounds__(256, 2)
sgemm_bias_f32x2(const float* __restrict__ A, const float* __restrict__ Wm,
                 const float* __restrict__ bias, float* __restrict__ C,
                 int rows, int ncols)
{
    __shared__ unsigned long long As[16][128];   // duplicated pairs, 16 KB
    __shared__ float              Bs[16][128];   // 8 KB

    const int tid = threadIdx.x;
    const int tx  = tid & 15;          // col group: cols tx*8 .. tx*8+7
    const int ty  = tid >> 4;          // row group: rows ty*8 .. ty*8+7
    const int rowBase = blockIdx.x * 128;
    const int colBase = blockIdx.y * 128;

    // A loader: each thread loads 8 floats of one row (2 float4)
    const int lr  = tid & 127;              // tile row 0..127
    const int lkg = (tid >> 7) * 8;         // k sub-offset 0 or 8
    const int  grow = rowBase + lr;
    const bool aOk  = (grow < rows);
    const float* Aptr = A + (size_t)grow * 256 + lkg;

    // B loader: thread (bk, bc) loads 8 consecutive cols of W row kb+bk
    const int bk = tid >> 4;                // 0..15
    const int bc = (tid & 15) * 8;          // 0..120
    const float* Bptr = Wm + (size_t)bk * ncols + colBase + bc;

    unsigned long long acc[8][4];
    #pragma unroll
    for (int i = 0; i < 8; i++)
        #pragma unroll
        for (int j = 0; j < 4; j++) acc[i][j] = 0ull;

    for (int kb = 0; kb < 256; kb += 16) {
        float4 a0 = aOk ? *(const float4*)(Aptr + kb)     : make_float4(0,0,0,0);
        float4 a1 = aOk ? *(const float4*)(Aptr + kb + 4) : make_float4(0,0,0,0);
        float4 b0 = *(const float4*)(Bptr + (size_t)kb * ncols);
        float4 b1 = *(const float4*)(Bptr + (size_t)kb * ncols + 4);

        As[lkg + 0][lr] = pack2(a0.x, a0.x);
        As[lkg + 1][lr] = pack2(a0.y, a0.y);
        As[lkg + 2][lr] = pack2(a0.z, a0.z);
        As[lkg + 3][lr] = pack2(a0.w, a0.w);
        As[lkg + 4][lr] = pack2(a1.x, a1.x);
        As[lkg + 5][lr] = pack2(a1.y, a1.y);
        As[lkg + 6][lr] = pack2(a1.z, a1.z);
        As[lkg + 7][lr] = pack2(a1.w, a1.w);
        *(float4*)&Bs[bk][bc]     = b0;
        *(float4*)&Bs[bk][bc + 4] = b1;
        __syncthreads();

        #pragma unroll
        for (int k = 0; k < 16; k++) {
            ulonglong2 a01 = *(const ulonglong2*)&As[k][ty * 8 + 0];
            ulonglong2 a23 = *(const ulonglong2*)&As[k][ty * 8 + 2];
            ulonglong2 a45 = *(const ulonglong2*)&As[k][ty * 8 + 4];
            ulonglong2 a67 = *(const ulonglong2*)&As[k][ty * 8 + 6];
            ulonglong2 b01 = *(const ulonglong2*)&Bs[k][tx * 8 + 0];
            ulonglong2 b23 = *(const ulonglong2*)&Bs[k][tx * 8 + 4];
            unsigned long long ap[8] = {a01.x, a01.y, a23.x, a23.y,
                                        a45.x, a45.y, a67.x, a67.y};
            unsigned long long bp[4] = {b01.x, b01.y, b23.x, b23.y};
            #pragma unroll
            for (int i = 0; i < 8; i++)
                #pragma unroll
                for (int j = 0; j < 4; j++)
                    FMA2(acc[i][j], ap[i], bp[j]);
        }
        __syncthreads();
    }

    // Epilogue: unpack pairs, add bias, vectorized store with row guard
    float4 bv0 = *(const float4*)(bias + colBase + tx * 8);
    float4 bv1 = *(const float4*)(bias + colBase + tx * 8 + 4);
    #pragma unroll
    for (int i = 0; i < 8; i++) {
        int r = rowBase + ty * 8 + i;
        if (r < rows) {
            float2 c0 = *(float2*)&acc[i][0];
            float2 c1 = *(float2*)&acc[i][1];
            float2 c2 = *(float2*)&acc[i][2];
            float2 c3 = *(float2*)&acc[i][3];
            float4 o0 = make_float4(c0.x + bv0.x, c0.y + bv0.y,
                                    c1.x + bv0.z, c1.y + bv0.w);
            float4 o1 = make_float4(c2.x + bv1.x, c2.y + bv1.y,
                                    c3.x + bv1.z, c3.y + bv1.w);
            float* Cp = C + (size_t)r * ncols + colBase + tx * 8;
            *(float4*)(Cp)     = o0;
            *(float4*)(Cp + 4) = o1;
        }
    }
}

// ---------------------------------------------------------------------------
// Fused softmax + deformable bilinear sampling, lane-distributed setup.
// One warp per (row, head). Lanes 0-15 each compute ONE point's 4 gather
// indices + 4 pre-scaled weights (validity folded in, division cancelled
// algebraically), staged to smem; then a branch-free broadcast gather loop.
// ---------------------------------------------------------------------------
__global__ void __launch_bounds__(256)
sample_kernel(const float* __restrict__ value,
              const float* __restrict__ offs,
              const float* __restrict__ alog,
              const float* __restrict__ refp,
              float* __restrict__ msout)
{
    __shared__ int4   sIdx[8][16];
    __shared__ float4 sWt [8][16];

    const int wid  = threadIdx.x >> 5;
    const int lane = threadIdx.x & 31;
    const int gwarp = blockIdx.x * 8 + wid;
    const int m   = gwarp & (MH - 1);
    const int row = gwarp >> 3;
    const int b   = (row >= LQ) ? 1 : 0;

    // ---- softmax over 16 (l,p) logits via warp shuffles ----
    const float* lg = alog + (size_t)row * 128 + m * 16;
    float v = (lane < 16) ? lg[lane] : -1e30f;
    float mx = v;
    #pragma unroll
    for (int o = 16; o; o >>= 1) mx = fmaxf(mx, __shfl_xor_sync(0xffffffffu, mx, o));
    float e = (lane < 16) ? expf(v - mx) : 0.f;
    float s = e;
    #pragma unroll
    for (int o = 16; o; o >>= 1) s += __shfl_xor_sync(0xffffffffu, s, o);
    const float inv = 1.f / s;

    // ---- per-point setup: lane p handles point (l = p>>2, p&3) ----
    if (lane < 16) {
        const int l  = lane >> 2;
        const int H  = c_H[l];
        const int W  = c_W[l];
        const int st = c_ST[l];
        const float fW = (float)W, fH = (float)H;

        const float rx = refp[(row * 4 + l) * 2 + 0];
        const float ry = refp[(row * 4 + l) * 2 + 1];
        const float* od = offs + (size_t)row * 256 + m * 32 + lane * 2;
        const float ox = od[0], oy = od[1];

        // Algebraic simplification of the reference chain:
        //   x = ((2*(rx + ox/W) - 1 + 1)*W - 1)*0.5 = rx*W + ox - 0.5
        const float x = fmaf(rx, fW, ox) - 0.5f;
        const float y = fmaf(ry, fH, oy) - 0.5f;

        const float x0f = floorf(x), y0f = floorf(y);
        const float fx = x - x0f, fy = y - y0f;
        const int ix = (int)x0f, iy = (int)y0f;

        const float lw = e * inv;                 // softmax attention weight
        float w00 = (1.f - fx) * (1.f - fy) * lw;
        float w01 = fx * (1.f - fy) * lw;
        float w10 = (1.f - fx) * fy * lw;
        float w11 = fx * fy * lw;

        const bool vx0 = (ix >= 0) && (ix < W);
        const bool vx1 = (ix + 1 >= 0) && (ix + 1 < W);
        const bool vy0 = (iy >= 0) && (iy < H);
        const bool vy1 = (iy + 1 >= 0) && (iy + 1 < H);
        if (!(vx0 && vy0)) w00 = 0.f;
        if (!(vx1 && vy0)) w01 = 0.f;
        if (!(vx0 && vy1)) w10 = 0.f;
        if (!(vx1 && vy1)) w11 = 0.f;

        const int cx0 = min(max(ix, 0), W - 1);
        const int cx1 = min(max(ix + 1, 0), W - 1);
        const int cy0 = min(max(iy, 0), H - 1);
        const int cy1 = min(max(iy + 1, 0), H - 1);
        const int r0 = st + cy0 * W;
        const int r1 = st + cy1 * W;

        sIdx[wid][lane] = make_int4((r0 + cx0) * 256, (r0 + cx1) * 256,
                                    (r1 + cx0) * 256, (r1 + cx1) * 256);
        sWt [wid][lane] = make_float4(w00, w01, w10, w11);
    }
    __syncwarp();

    // ---- branch-free gather loop: lane = channel, 4 coalesced 128B gathers ----
    const float* vb = value + (size_t)b * LQ * 256 + m * 32 + lane;
    float a0 = 0.f, a1 = 0.f, a2 = 0.f, a3 = 0.f;
    #pragma unroll
    for (int p = 0; p < 16; p++) {
        const int4   I  = sIdx[wid][p];
        const float4 Wt = sWt[wid][p];
        a0 = fmaf(Wt.x, vb[I.x], a0);
        a1 = fmaf(Wt.y, vb[I.y], a1);
        a2 = fmaf(Wt.z, vb[I.z], a2);
        a3 = fmaf(Wt.w, vb[I.w], a3);
    }
    msout[(size_t)row * 256 + m * 32 + lane] = (a0 + a1) + (a2 + a3);
}

// ---------------------------------------------------------------------------
// Launch: 5 graph-capturable kernel launches on the default stream.
// ---------------------------------------------------------------------------
extern "C" void kernel_launch(void* const* d_in, const int* in_sizes, int n_in,
                              void* d_out, int out_size)
{
    (void)in_sizes; (void)n_in; (void)out_size;

    const float* query = (const float*)d_in[0];
    const float* refp  = (const float*)d_in[1];
    const float* inpf  = (const float*)d_in[2];
    // d_in[3] = spatial_shapes (hardcoded)
    const float* Wv = (const float*)d_in[4];
    const float* bv = (const float*)d_in[5];
    const float* Ws = (const float*)d_in[6];
    const float* bs = (const float*)d_in[7];
    const float* Wa = (const float*)d_in[8];
    const float* ba = (const float*)d_in[9];
    const float* Wo = (const float*)d_in[10];
    const float* bo = (const float*)d_in[11];
    float* out = (float*)d_out;

    float *value, *offs, *alog, *msout;
    cudaGetSymbolAddress((void**)&value, g_value);
    cudaGetSymbolAddress((void**)&offs,  g_offs);
    cudaGetSymbolAddress((void**)&alog,  g_alog);
    cudaGetSymbolAddress((void**)&msout, g_msout);

    const dim3 blk(256);
    const dim3 g256((ROWS + 127) / 128, 2);   // N = 256
    const dim3 g128((ROWS + 127) / 128, 1);   // N = 128

    // 1) value = input_flatten @ Wv + bv
    sgemm_bias_f32x2<<<g256, blk>>>(inpf, Wv, bv, value, ROWS, 256);
    // 2) sampling offsets = query @ Ws + bs
    sgemm_bias_f32x2<<<g256, blk>>>(query, Ws, bs, offs, ROWS, 256);
    // 3) attention logits = query @ Wa + ba
    sgemm_bias_f32x2<<<g128, blk>>>(query, Wa, ba, alog, ROWS, 128);
    // 4) fused softmax + deformable bilinear sampling
    sample_kernel<<<ROWS, blk>>>(value, offs, alog, refp, msout);
    // 5) out = msout @ Wo + bo
    sgemm_bias_f32x2<<<g256, blk>>>(msout, Wo, bo, out, ROWS, 256);
}

// round 8
// speedup vs baseline: 1.5176x; 1.1481x over previous
#include <cuda_runtime.h>
#include <cuda_bf16.h>
#include <math.h>
#include <stdint.h>

// ---------------------------------------------------------------------------
// Problem constants
// ---------------------------------------------------------------------------
#define BB   2
#define LQ   12240
#define DMO  256
#define MH   8
#define ROWS (BB * LQ)     // 24480

__device__ __constant__ int c_H[4]  = {96, 48, 24, 12};
__device__ __constant__ int c_W[4]  = {96, 48, 24, 12};
__device__ __constant__ int c_ST[4] = {0, 9216, 11520, 12096};

// ---------------------------------------------------------------------------
// Scratch (static device globals: allocation-free, graph-safe)
// ---------------------------------------------------------------------------
__device__ float g_value[ROWS * DMO];
__device__ float g_offs [ROWS * DMO];
__device__ float g_alog [ROWS * 128];
__device__ float g_msout[ROWS * DMO];

// ---------------------------------------------------------------------------
// tf32 helpers
// ---------------------------------------------------------------------------
// Split a into (hi, lo) tf32 values: hi = rna(a), lo = rna(a - hi).
__device__ __forceinline__ float2 tf32_pair(float a) {
    uint32_t h;
    asm("cvt.rna.tf32.f32 %0, %1;" : "=r"(h) : "f"(a));
    float hf = __uint_as_float(h);
    float lf = a - hf;
    uint32_t l;
    asm("cvt.rna.tf32.f32 %0, %1;" : "=r"(l) : "f"(lf));
    return make_float2(hf, __uint_as_float(l));
}

// m16n8k8 tf32 MMA: D(16x8,f32) += A(16x8) * B(8x8)
__device__ __forceinline__ void mma_tf32(float4& c,
                                         uint32_t a0, uint32_t a1, uint32_t a2, uint32_t a3,
                                         uint32_t b0, uint32_t b1) {
    asm volatile(
        "mma.sync.aligned.m16n8k8.row.col.f32.tf32.tf32.f32 "
        "{%0,%1,%2,%3}, {%4,%5,%6,%7}, {%8,%9}, {%0,%1,%2,%3};"
        : "+f"(c.x), "+f"(c.y), "+f"(c.z), "+f"(c.w)
        : "r"(a0), "r"(a1), "r"(a2), "r"(a3), "r"(b0), "r"(b1));
}

#define FB(x) (__float_as_uint(x))

// ---------------------------------------------------------------------------
// tf32 tensor-core GEMM + bias (3-term split, near-fp32 accuracy)
// C[rows x ncols] = A[rows x 256] @ W[256 x ncols] + bias
// Block tile 128x64, 8 warps = 4(M) x 2(N), warp tile 32x32.
// Smem fragment layout: per (row, kstep, c) a float4 {hi_c, lo_c, hi_c+4, lo_c+4}
// at exactly the lane's fragment address -> inner loop = LDS.128 + HMMA only.
// Row stride padded to 68 floats for conflict-free fragment loads.
// ---------------------------------------------------------------------------
#define AS_STRIDE 68
#define GEMM_SMEM ((128 * AS_STRIDE + 64 * AS_STRIDE) * 4)   // 52224 B

__global__ void __launch_bounds__(256)
gemm_tf32(const float* __restrict__ A, const float* __restrict__ Wm,
          const float* __restrict__ bias, float* __restrict__ C,
          int rows, int ncols)
{
    extern __shared__ char smem[];
    float* As = (float*)smem;                               // 128 x 68
    float* Bs = (float*)(smem + 128 * AS_STRIDE * 4);       // 64 x 68

    const int tid  = threadIdx.x;
    const int lane = tid & 31;
    const int wid  = tid >> 5;
    const int wm   = wid & 3;          // warp M position (0..3) -> rows wm*32
    const int wn   = wid >> 2;         // warp N position (0..1) -> cols wn*32
    const int r    = lane >> 2;        // fragment row-in-group 0..7
    const int tig  = lane & 3;         // thread-in-group 0..3

    const int rowBase = blockIdx.x * 128;
    const int colBase = blockIdx.y * 64;

    float4 Cacc[2][4];
    #pragma unroll
    for (int mt = 0; mt < 2; mt++)
        #pragma unroll
        for (int nt = 0; nt < 4; nt++)
            Cacc[mt][nt] = make_float4(0.f, 0.f, 0.f, 0.f);

    const float* aP = As + (wm * 32 + r) * AS_STRIDE + tig * 4;
    const float* bP = Bs + (wn * 32 + r) * AS_STRIDE + tig * 4;

    for (int kb = 0; kb < 8; kb++) {       // 8 K-chunks of 32
        if (kb) __syncthreads();           // protect smem reuse

        // ---- stage A: 128 rows x 32 k, hi/lo interleaved fragment layout ----
        #pragma unroll
        for (int it = 0; it < 8; it++) {
            int gidx = it * 256 + tid;     // 2048 slots
            int row  = gidx >> 4;
            int s    = gidx & 15;
            int ks   = s >> 2, c = s & 3;
            int grow = rowBase + row;
            int k0   = kb * 32 + ks * 8 + c;
            float v0 = 0.f, v1 = 0.f;
            if (grow < rows) {
                const float* ap = A + (size_t)grow * 256 + k0;
                v0 = ap[0];
                v1 = ap[4];
            }
            float2 p0 = tf32_pair(v0);
            float2 p1 = tf32_pair(v1);
            *(float4*)&As[row * AS_STRIDE + ks * 16 + c * 4] =
                make_float4(p0.x, p0.y, p1.x, p1.y);
        }

        // ---- stage B: 32 k x 64 n, same fragment layout (indexed by n) ----
        #pragma unroll
        for (int it = 0; it < 4; it++) {
            int gidx = it * 256 + tid;     // 1024 slots
            int n  = gidx & 63;
            int s  = gidx >> 6;
            int ks = s >> 2, c = s & 3;
            int k  = kb * 32 + ks * 8 + c;
            const float* wp = Wm + (size_t)k * ncols + colBase + n;
            float v0 = wp[0];
            float v1 = wp[(size_t)4 * ncols];
            float2 p0 = tf32_pair(v0);
            float2 p1 = tf32_pair(v1);
            *(float4*)&Bs[n * AS_STRIDE + ks * 16 + c * 4] =
                make_float4(p0.x, p0.y, p1.x, p1.y);
        }
        __syncthreads();

        // ---- compute: 4 k-steps of m16n8k8, 3-term split ----
        #pragma unroll
        for (int ks = 0; ks < 4; ks++) {
            const int ko = ks * 16;
            float4 a0r  = *(const float4*)(aP + ko);
            float4 a0r8 = *(const float4*)(aP + 8  * AS_STRIDE + ko);
            float4 a1r  = *(const float4*)(aP + 16 * AS_STRIDE + ko);
            float4 a1r8 = *(const float4*)(aP + 24 * AS_STRIDE + ko);

            // fragment regs: a0=(r,c) a1=(r+8,c) a2=(r,c+4) a3=(r+8,c+4)
            uint32_t ah[2][4] = {
                { FB(a0r.x), FB(a0r8.x), FB(a0r.z), FB(a0r8.z) },
                { FB(a1r.x), FB(a1r8.x), FB(a1r.z), FB(a1r8.z) } };
            uint32_t al[2][4] = {
                { FB(a0r.y), FB(a0r8.y), FB(a0r.w), FB(a0r8.w) },
                { FB(a1r.y), FB(a1r8.y), FB(a1r.w), FB(a1r8.w) } };

            #pragma unroll
            for (int nt = 0; nt < 4; nt++) {
                float4 bv = *(const float4*)(bP + nt * 8 * AS_STRIDE + ko);
                uint32_t bh0 = FB(bv.x), bh1 = FB(bv.z);
                uint32_t bl0 = FB(bv.y), bl1 = FB(bv.w);
                #pragma unroll
                for (int mt = 0; mt < 2; mt++) {
                    mma_tf32(Cacc[mt][nt], ah[mt][0], ah[mt][1], ah[mt][2], ah[mt][3], bh0, bh1);
                    mma_tf32(Cacc[mt][nt], al[mt][0], al[mt][1], al[mt][2], al[mt][3], bh0, bh1);
                    mma_tf32(Cacc[mt][nt], ah[mt][0], ah[mt][1], ah[mt][2], ah[mt][3], bl0, bl1);
                }
            }
        }
    }

    // ---- epilogue: +bias, float2 stores ----
    #pragma unroll
    for (int nt = 0; nt < 4; nt++) {
        const int col = colBase + wn * 32 + nt * 8 + tig * 2;
        const float b0 = bias[col], b1 = bias[col + 1];
        #pragma unroll
        for (int mt = 0; mt < 2; mt++) {
            const int row0 = rowBase + wm * 32 + mt * 16 + r;
            const float4 c4 = Cacc[mt][nt];
            if (row0 < rows)
                *(float2*)(C + (size_t)row0 * ncols + col) =
                    make_float2(c4.x + b0, c4.y + b1);
            if (row0 + 8 < rows)
                *(float2*)(C + (size_t)(row0 + 8) * ncols + col) =
                    make_float2(c4.z + b0, c4.w + b1);
        }
    }
}

// ---------------------------------------------------------------------------
// Fused softmax + deformable bilinear sampling (unchanged from R6: 151us)
// ---------------------------------------------------------------------------
__global__ void __launch_bounds__(256)
sample_kernel(const float* __restrict__ value,
              const float* __restrict__ offs,
              const float* __restrict__ alog,
              const float* __restrict__ refp,
              float* __restrict__ msout)
{
    __shared__ int4   sIdx[8][16];
    __shared__ float4 sWt [8][16];

    const int wid  = threadIdx.x >> 5;
    const int lane = threadIdx.x & 31;
    const int gwarp = blockIdx.x * 8 + wid;
    const int m   = gwarp & (MH - 1);
    const int row = gwarp >> 3;
    const int b   = (row >= LQ) ? 1 : 0;

    const float* lg = alog + (size_t)row * 128 + m * 16;
    float v = (lane < 16) ? lg[lane] : -1e30f;
    float mx = v;
    #pragma unroll
    for (int o = 16; o; o >>= 1) mx = fmaxf(mx, __shfl_xor_sync(0xffffffffu, mx, o));
    float e = (lane < 16) ? expf(v - mx) : 0.f;
    float s = e;
    #pragma unroll
    for (int o = 16; o; o >>= 1) s += __shfl_xor_sync(0xffffffffu, s, o);
    const float inv = 1.f / s;

    if (lane < 16) {
        const int l  = lane >> 2;
        const int H  = c_H[l];
        const int W  = c_W[l];
        const int st = c_ST[l];
        const float fW = (float)W, fH = (float)H;

        const float rx = refp[(row * 4 + l) * 2 + 0];
        const float ry = refp[(row * 4 + l) * 2 + 1];
        const float* od = offs + (size_t)row * 256 + m * 32 + lane * 2;
        const float ox = od[0], oy = od[1];

        const float x = fmaf(rx, fW, ox) - 0.5f;
        const float y = fmaf(ry, fH, oy) - 0.5f;

        const float x0f = floorf(x), y0f = floorf(y);
        const float fx = x - x0f, fy = y - y0f;
        const int ix = (int)x0f, iy = (int)y0f;

        const float lw = e * inv;
        float w00 = (1.f - fx) * (1.f - fy) * lw;
        float w01 = fx * (1.f - fy) * lw;
        float w10 = (1.f - fx) * fy * lw;
        float w11 = fx * fy * lw;

        const bool vx0 = (ix >= 0) && (ix < W);
        const bool vx1 = (ix + 1 >= 0) && (ix + 1 < W);
        const bool vy0 = (iy >= 0) && (iy < H);
        const bool vy1 = (iy + 1 >= 0) && (iy + 1 < H);
        if (!(vx0 && vy0)) w00 = 0.f;
        if (!(vx1 && vy0)) w01 = 0.f;
        if (!(vx0 && vy1)) w10 = 0.f;
        if (!(vx1 && vy1)) w11 = 0.f;

        const int cx0 = min(max(ix, 0), W - 1);
        const int cx1 = min(max(ix + 1, 0), W - 1);
        const int cy0 = min(max(iy, 0), H - 1);
        const int cy1 = min(max(iy + 1, 0), H - 1);
        const int r0 = st + cy0 * W;
        const int r1 = st + cy1 * W;

        sIdx[wid][lane] = make_int4((r0 + cx0) * 256, (r0 + cx1) * 256,
                                    (r1 + cx0) * 256, (r1 + cx1) * 256);
        sWt [wid][lane] = make_float4(w00, w01, w10, w11);
    }
    __syncwarp();

    const float* vb = value + (size_t)b * LQ * 256 + m * 32 + lane;
    float a0 = 0.f, a1 = 0.f, a2 = 0.f, a3 = 0.f;
    #pragma unroll
    for (int p = 0; p < 16; p++) {
        const int4   I  = sIdx[wid][p];
        const float4 Wt = sWt[wid][p];
        a0 = fmaf(Wt.x, vb[I.x], a0);
        a1 = fmaf(Wt.y, vb[I.y], a1);
        a2 = fmaf(Wt.z, vb[I.z], a2);
        a3 = fmaf(Wt.w, vb[I.w], a3);
    }
    msout[(size_t)row * 256 + m * 32 + lane] = (a0 + a1) + (a2 + a3);
}

// ---------------------------------------------------------------------------
// Launch
// ---------------------------------------------------------------------------
extern "C" void kernel_launch(void* const* d_in, const int* in_sizes, int n_in,
                              void* d_out, int out_size)
{
    (void)in_sizes; (void)n_in; (void)out_size;

    const float* query = (const float*)d_in[0];
    const float* refp  = (const float*)d_in[1];
    const float* inpf  = (const float*)d_in[2];
    const float* Wv = (const float*)d_in[4];
    const float* bv = (const float*)d_in[5];
    const float* Ws = (const float*)d_in[6];
    const float* bs = (const float*)d_in[7];
    const float* Wa = (const float*)d_in[8];
    const float* ba = (const float*)d_in[9];
    const float* Wo = (const float*)d_in[10];
    const float* bo = (const float*)d_in[11];
    float* out = (float*)d_out;

    float *value, *offs, *alog, *msout;
    cudaGetSymbolAddress((void**)&value, g_value);
    cudaGetSymbolAddress((void**)&offs,  g_offs);
    cudaGetSymbolAddress((void**)&alog,  g_alog);
    cudaGetSymbolAddress((void**)&msout, g_msout);

    cudaFuncSetAttribute(gemm_tf32, cudaFuncAttributeMaxDynamicSharedMemorySize,
                         GEMM_SMEM);

    const dim3 blk(256);
    const int  mTiles = (ROWS + 127) / 128;        // 192
    const dim3 g256(mTiles, 4);                    // N = 256
    const dim3 g128(mTiles, 2);                    // N = 128

    gemm_tf32<<<g256, blk, GEMM_SMEM>>>(inpf,  Wv, bv, value, ROWS, 256);
    gemm_tf32<<<g256, blk, GEMM_SMEM>>>(query, Ws, bs, offs,  ROWS, 256);
    gemm_tf32<<<g128, blk, GEMM_SMEM>>>(query, Wa, ba, alog,  ROWS, 128);
    sample_kernel<<<ROWS, blk>>>(value, offs, alog, refp, msout);
    gemm_tf32<<<g256, blk, GEMM_SMEM>>>(msout, Wo, bo, out,   ROWS, 256);
}

// round 9
// speedup vs baseline: 2.2907x; 1.5094x over previous
#include <cuda_runtime.h>
#include <cuda_bf16.h>
#include <math.h>
#include <stdint.h>

// ---------------------------------------------------------------------------
// Problem constants
// ---------------------------------------------------------------------------
#define BB   2
#define LQ   12240
#define DMO  256
#define MH   8
#define ROWS (BB * LQ)     // 24480

__device__ __constant__ int c_H[4]  = {96, 48, 24, 12};
__device__ __constant__ int c_W[4]  = {96, 48, 24, 12};
__device__ __constant__ int c_ST[4] = {0, 9216, 11520, 12096};

// ---------------------------------------------------------------------------
// Scratch (static device globals: allocation-free, graph-safe)
// ---------------------------------------------------------------------------
__device__ float g_value[ROWS * DMO];
__device__ float g_offs [ROWS * DMO];
__device__ float g_alog [ROWS * 128];
__device__ float g_msout[ROWS * DMO];

// ---------------------------------------------------------------------------
// bf16 split helpers.
// hi = truncate-to-bf16 (rz) so lo = a - hi is EXACT in fp32; lo then rounds
// to bf16 capturing bits down to 2^-17 of a. 4-term MMA recovers ~fp32.
// Slot = {P0h, P0l, P1h, P1l} where P0 = k{2t,2t+1}, P1 = k{8+2t, 8+2t+1},
// each packed bf16x2 with the even-k element in the LOW half.
// ---------------------------------------------------------------------------
__device__ __forceinline__ uint4 split_pack(float2 p0, float2 p1) {
    uint32_t u0 = __float_as_uint(p0.x), u1 = __float_as_uint(p0.y);
    uint32_t u2 = __float_as_uint(p1.x), u3 = __float_as_uint(p1.y);
    uint32_t h0 = u0 & 0xFFFF0000u, h1 = u1 & 0xFFFF0000u;
    uint32_t h2 = u2 & 0xFFFF0000u, h3 = u3 & 0xFFFF0000u;
    float l0 = p0.x - __uint_as_float(h0);
    float l1 = p0.y - __uint_as_float(h1);
    float l2 = p1.x - __uint_as_float(h2);
    float l3 = p1.y - __uint_as_float(h3);
    uint4 r;
    r.x = __byte_perm(h0, h1, 0x7632);     // {h1>>16 : h0>>16}, even-k low
    asm("cvt.rn.bf16x2.f32 %0, %1, %2;" : "=r"(r.y) : "f"(l1), "f"(l0));
    r.z = __byte_perm(h2, h3, 0x7632);
    asm("cvt.rn.bf16x2.f32 %0, %1, %2;" : "=r"(r.w) : "f"(l3), "f"(l2));
    return r;
}

// m16n8k16 bf16 MMA: D(16x8,f32) += A(16x16) * B(16x8)
__device__ __forceinline__ void mma_bf16(float4& c,
                                         uint32_t a0, uint32_t a1, uint32_t a2, uint32_t a3,
                                         uint32_t b0, uint32_t b1) {
    asm volatile(
        "mma.sync.aligned.m16n8k16.row.col.f32.bf16.bf16.f32 "
        "{%0,%1,%2,%3}, {%4,%5,%6,%7}, {%8,%9}, {%0,%1,%2,%3};"
        : "+f"(c.x), "+f"(c.y), "+f"(c.z), "+f"(c.w)
        : "r"(a0), "r"(a1), "r"(a2), "r"(a3), "r"(b0), "r"(b1));
}

// ---------------------------------------------------------------------------
// bf16 4-term tensor-core GEMM + bias (near-fp32 accuracy)
// C[rows x ncols] = A[rows x 256] @ W[256 x ncols] + bias
// Block tile 128x64, 8 warps = 4(M) x 2(N), warp tile 32x32. K chunk = 32.
// Dual-output: blockIdx.y < ytiles0 -> (W0,bias0,C0,ncols0), else set 1.
// Smem rows are 192B (12 uint4): conflict-free LDS.128 for fragments.
// ---------------------------------------------------------------------------
__global__ void __launch_bounds__(256)
gemm_bf16(const float* __restrict__ A, int rows,
          const float* __restrict__ W0, const float* __restrict__ bias0,
          float* __restrict__ C0, int ncols0, int ytiles0,
          const float* __restrict__ W1, const float* __restrict__ bias1,
          float* __restrict__ C1, int ncols1)
{
    __shared__ uint4 As4[128 * 12];   // 24576 B
    __shared__ uint4 Bs4[64 * 12];    // 12288 B

    const float* Wm;  const float* bias;  float* C;  int ncols, colBase;
    if ((int)blockIdx.y < ytiles0) {
        Wm = W0; bias = bias0; C = C0; ncols = ncols0; colBase = blockIdx.y * 64;
    } else {
        Wm = W1; bias = bias1; C = C1; ncols = ncols1;
        colBase = (blockIdx.y - ytiles0) * 64;
    }

    const int tid  = threadIdx.x;
    const int lane = tid & 31;
    const int wid  = tid >> 5;
    const int wm   = wid & 3;          // warp M position: rows wm*32
    const int wn   = wid >> 2;         // warp N position: cols wn*32
    const int r    = lane >> 2;        // fragment row 0..7
    const int tig  = lane & 3;         // thread-in-group

    const int rowBase = blockIdx.x * 128;

    float4 acc[2][4];
    #pragma unroll
    for (int mt = 0; mt < 2; mt++)
        #pragma unroll
        for (int nt = 0; nt < 4; nt++)
            acc[mt][nt] = make_float4(0.f, 0.f, 0.f, 0.f);

    for (int kb = 0; kb < 8; kb++) {           // 8 K-chunks of 32
        const int k0 = kb * 32;
        if (kb) __syncthreads();

        // ---- stage A: 1024 slots (128 rows x 2 ksteps x 4 tig), 4/thread ----
        #pragma unroll
        for (int it = 0; it < 4; it++) {
            int slot = it * 256 + tid;
            int row  = slot >> 3;
            int s    = (slot >> 2) & 1;
            int t    = slot & 3;
            int grow = rowBase + row;
            float2 p0 = make_float2(0.f, 0.f), p1 = make_float2(0.f, 0.f);
            if (grow < rows) {
                const float* ap = A + (size_t)grow * 256 + k0 + s * 16 + 2 * t;
                p0 = *(const float2*)ap;
                p1 = *(const float2*)(ap + 8);
            }
            As4[row * 12 + s * 4 + t] = split_pack(p0, p1);
        }

        // ---- stage B: 512 slots (8 (s,t) x 64 cols), 2/thread, coalesced ----
        #pragma unroll
        for (int it = 0; it < 2; it++) {
            int slot = it * 256 + tid;
            int n  = slot & 63;
            int st = slot >> 6;
            int s  = st >> 2;
            int t  = st & 3;
            const float* wp = Wm + (size_t)(k0 + s * 16 + 2 * t) * ncols + colBase + n;
            float2 p0 = make_float2(wp[0], wp[ncols]);
            float2 p1 = make_float2(wp[8 * ncols], wp[9 * ncols]);
            Bs4[n * 12 + s * 4 + t] = split_pack(p0, p1);
        }
        __syncthreads();

        // ---- compute: 2 ksteps of m16n8k16, 4-term split ----
        #pragma unroll
        for (int s = 0; s < 2; s++) {
            uint4 aw[2][2];
            #pragma unroll
            for (int mt = 0; mt < 2; mt++) {
                const int ar = wm * 32 + mt * 16 + r;
                aw[mt][0] = As4[ar * 12 + s * 4 + tig];
                aw[mt][1] = As4[(ar + 8) * 12 + s * 4 + tig];
            }
            #pragma unroll
            for (int nt = 0; nt < 4; nt++) {
                uint4 bw = Bs4[(wn * 32 + nt * 8 + r) * 12 + s * 4 + tig];
                #pragma unroll
                for (int mt = 0; mt < 2; mt++) {
                    mma_bf16(acc[mt][nt], aw[mt][0].x, aw[mt][1].x, aw[mt][0].z, aw[mt][1].z, bw.x, bw.z);
                    mma_bf16(acc[mt][nt], aw[mt][0].y, aw[mt][1].y, aw[mt][0].w, aw[mt][1].w, bw.x, bw.z);
                    mma_bf16(acc[mt][nt], aw[mt][0].x, aw[mt][1].x, aw[mt][0].z, aw[mt][1].z, bw.y, bw.w);
                    mma_bf16(acc[mt][nt], aw[mt][0].y, aw[mt][1].y, aw[mt][0].w, aw[mt][1].w, bw.y, bw.w);
                }
            }
        }
    }

    // ---- epilogue: +bias, float2 stores ----
    #pragma unroll
    for (int nt = 0; nt < 4; nt++) {
        const int col = colBase + wn * 32 + nt * 8 + tig * 2;
        const float b0 = bias[col], b1 = bias[col + 1];
        #pragma unroll
        for (int mt = 0; mt < 2; mt++) {
            const int row0 = rowBase + wm * 32 + mt * 16 + r;
            const float4 c4 = acc[mt][nt];
            if (row0 < rows)
                *(float2*)(C + (size_t)row0 * ncols + col) =
                    make_float2(c4.x + b0, c4.y + b1);
            if (row0 + 8 < rows)
                *(float2*)(C + (size_t)(row0 + 8) * ncols + col) =
                    make_float2(c4.z + b0, c4.w + b1);
        }
    }
}

// ---------------------------------------------------------------------------
// Fused softmax + deformable bilinear sampling, v2.
// One warp per (row, head). Setup as before (lanes 0-15 -> smem).
// Gather: 4 lane-groups of 8; group g handles points 4g..4g+3 over ALL 32
// channels (8 lanes x float4). Cross-group butterfly (shfl_xor 8,16) sums the
// partials; lanes 0-7 store float4. LDG instrs 64->16, IMAD 64->16.
// ---------------------------------------------------------------------------
__global__ void __launch_bounds__(256)
sample_kernel(const float* __restrict__ value,
              const float* __restrict__ offs,
              const float* __restrict__ alog,
              const float* __restrict__ refp,
              float* __restrict__ msout)
{
    __shared__ int4   sIdx[8][16];
    __shared__ float4 sWt [8][16];

    const int wid  = threadIdx.x >> 5;
    const int lane = threadIdx.x & 31;
    const int m    = wid;
    const int row  = blockIdx.x;
    const int b    = (row >= LQ) ? 1 : 0;

    // ---- softmax over 16 (l,p) logits via warp shuffles ----
    const float* lg = alog + (size_t)row * 128 + m * 16;
    float v = (lane < 16) ? lg[lane] : -1e30f;
    float mx = v;
    #pragma unroll
    for (int o = 16; o; o >>= 1) mx = fmaxf(mx, __shfl_xor_sync(0xffffffffu, mx, o));
    float e = (lane < 16) ? expf(v - mx) : 0.f;
    float s = e;
    #pragma unroll
    for (int o = 16; o; o >>= 1) s += __shfl_xor_sync(0xffffffffu, s, o);
    const float inv = 1.f / s;

    // ---- per-point setup: lane p handles point (l = p>>2, p&3) ----
    if (lane < 16) {
        const int l  = lane >> 2;
        const int H  = c_H[l];
        const int W  = c_W[l];
        const int st = c_ST[l];
        const float fW = (float)W, fH = (float)H;

        const float rx = refp[(row * 4 + l) * 2 + 0];
        const float ry = refp[(row * 4 + l) * 2 + 1];
        const float* od = offs + (size_t)row * 256 + m * 32 + lane * 2;
        const float ox = od[0], oy = od[1];

        // Algebraic collapse of the reference chain: x = rx*W + ox - 0.5
        const float x = fmaf(rx, fW, ox) - 0.5f;
        const float y = fmaf(ry, fH, oy) - 0.5f;

        const float x0f = floorf(x), y0f = floorf(y);
        const float fx = x - x0f, fy = y - y0f;
        const int ix = (int)x0f, iy = (int)y0f;

        const float lw = e * inv;
        float w00 = (1.f - fx) * (1.f - fy) * lw;
        float w01 = fx * (1.f - fy) * lw;
        float w10 = (1.f - fx) * fy * lw;
        float w11 = fx * fy * lw;

        const bool vx0 = (ix >= 0) && (ix < W);
        const bool vx1 = (ix + 1 >= 0) && (ix + 1 < W);
        const bool vy0 = (iy >= 0) && (iy < H);
        const bool vy1 = (iy + 1 >= 0) && (iy + 1 < H);
        if (!(vx0 && vy0)) w00 = 0.f;
        if (!(vx1 && vy0)) w01 = 0.f;
        if (!(vx0 && vy1)) w10 = 0.f;
        if (!(vx1 && vy1)) w11 = 0.f;

        const int cx0 = min(max(ix, 0), W - 1);
        const int cx1 = min(max(ix + 1, 0), W - 1);
        const int cy0 = min(max(iy, 0), H - 1);
        const int cy1 = min(max(iy + 1, 0), H - 1);
        const int r0 = st + cy0 * W;
        const int r1 = st + cy1 * W;

        sIdx[wid][lane] = make_int4((r0 + cx0) * 256, (r0 + cx1) * 256,
                                    (r1 + cx0) * 256, (r1 + cx1) * 256);
        sWt [wid][lane] = make_float4(w00, w01, w10, w11);
    }
    __syncwarp();

    // ---- gather: group g (8 lanes, float4 = 32 channels) does 4 points ----
    const int g  = lane >> 3;
    const int c4 = (lane & 7) * 4;
    const float* vb4 = value + (size_t)b * LQ * 256 + m * 32 + c4;

    float4 acc = make_float4(0.f, 0.f, 0.f, 0.f);
    #pragma unroll
    for (int pp = 0; pp < 4; pp++) {
        const int p = g * 4 + pp;
        const int4   I  = sIdx[wid][p];
        const float4 Wt = sWt[wid][p];
        float4 s0 = *(const float4*)(vb4 + I.x);
        float4 s1 = *(const float4*)(vb4 + I.y);
        float4 s2 = *(const float4*)(vb4 + I.z);
        float4 s3 = *(const float4*)(vb4 + I.w);
        acc.x = fmaf(Wt.x, s0.x, fmaf(Wt.y, s1.x, fmaf(Wt.z, s2.x, fmaf(Wt.w, s3.x, acc.x))));
        acc.y = fmaf(Wt.x, s0.y, fmaf(Wt.y, s1.y, fmaf(Wt.z, s2.y, fmaf(Wt.w, s3.y, acc.y))));
        acc.z = fmaf(Wt.x, s0.z, fmaf(Wt.y, s1.z, fmaf(Wt.z, s2.z, fmaf(Wt.w, s3.z, acc.z))));
        acc.w = fmaf(Wt.x, s0.w, fmaf(Wt.y, s1.w, fmaf(Wt.z, s2.w, fmaf(Wt.w, s3.w, acc.w))));
    }

    // ---- butterfly over the 4 groups (lane bits 3 and 4) ----
    #pragma unroll
    for (int o = 8; o <= 16; o <<= 1) {
        acc.x += __shfl_xor_sync(0xffffffffu, acc.x, o);
        acc.y += __shfl_xor_sync(0xffffffffu, acc.y, o);
        acc.z += __shfl_xor_sync(0xffffffffu, acc.z, o);
        acc.w += __shfl_xor_sync(0xffffffffu, acc.w, o);
    }

    if (lane < 8)
        *(float4*)(msout + (size_t)row * 256 + m * 32 + c4) = acc;
}

// ---------------------------------------------------------------------------
// Launch: 4 graph-capturable kernel launches.
// ---------------------------------------------------------------------------
extern "C" void kernel_launch(void* const* d_in, const int* in_sizes, int n_in,
                              void* d_out, int out_size)
{
    (void)in_sizes; (void)n_in; (void)out_size;

    const float* query = (const float*)d_in[0];
    const float* refp  = (const float*)d_in[1];
    const float* inpf  = (const float*)d_in[2];
    const float* Wv = (const float*)d_in[4];
    const float* bv = (const float*)d_in[5];
    const float* Ws = (const float*)d_in[6];
    const float* bs = (const float*)d_in[7];
    const float* Wa = (const float*)d_in[8];
    const float* ba = (const float*)d_in[9];
    const float* Wo = (const float*)d_in[10];
    const float* bo = (const float*)d_in[11];
    float* out = (float*)d_out;

    float *value, *offs, *alog, *msout;
    cudaGetSymbolAddress((void**)&value, g_value);
    cudaGetSymbolAddress((void**)&offs,  g_offs);
    cudaGetSymbolAddress((void**)&alog,  g_alog);
    cudaGetSymbolAddress((void**)&msout, g_msout);

    const dim3 blk(256);
    const int  mTiles = (ROWS + 127) / 128;        // 192

    // 1) value = input_flatten @ Wv + bv           (grid y = 4)
    gemm_bf16<<<dim3(mTiles, 4), blk>>>(inpf, ROWS,
                                        Wv, bv, value, 256, 4,
                                        Wv, bv, value, 256);
    // 2+3) offs = query @ Ws + bs ; alog = query @ Wa + ba   (fused, y = 6)
    gemm_bf16<<<dim3(mTiles, 6), blk>>>(query, ROWS,
                                        Ws, bs, offs, 256, 4,
                                        Wa, ba, alog, 128);
    // 4) fused softmax + deformable bilinear sampling
    sample_kernel<<<ROWS, blk>>>(value, offs, alog, refp, msout);
    // 5) out = msout @ Wo + bo                     (grid y = 4)
    gemm_bf16<<<dim3(mTiles, 4), blk>>>(msout, ROWS,
                                        Wo, bo, out, 256, 4,
                                        Wo, bo, out, 256);
}

// round 10
// speedup vs baseline: 2.5984x; 1.1343x over previous
#include <cuda_runtime.h>
#include <cuda_bf16.h>
#include <math.h>
#include <stdint.h>

// ---------------------------------------------------------------------------
// Problem constants
// ---------------------------------------------------------------------------
#define BB   2
#define LQ   12240
#define DMO  256
#define MH   8
#define ROWS (BB * LQ)     // 24480

__device__ __constant__ int c_H[4]  = {96, 48, 24, 12};
__device__ __constant__ int c_W[4]  = {96, 48, 24, 12};
__device__ __constant__ int c_ST[4] = {0, 9216, 11520, 12096};

// ---------------------------------------------------------------------------
// Scratch (static device globals: allocation-free, graph-safe)
// ---------------------------------------------------------------------------
__device__ float g_value[ROWS * DMO];
__device__ float g_offs [ROWS * DMO];
__device__ float g_alog [ROWS * 128];
__device__ float g_msout[ROWS * DMO];

// ---------------------------------------------------------------------------
// bf16 split helpers: hi = truncate-to-bf16 (exact residual), lo = rn(a-hi).
// Slot = {P0h, P0l, P1h, P1l}; P0 = k{2t,2t+1}, P1 = k{8+2t,8+2t+1},
// packed bf16x2 with even-k element in the LOW half.
// ---------------------------------------------------------------------------
__device__ __forceinline__ uint4 split_pack(float2 p0, float2 p1) {
    uint32_t h0 = __float_as_uint(p0.x) & 0xFFFF0000u;
    uint32_t h1 = __float_as_uint(p0.y) & 0xFFFF0000u;
    uint32_t h2 = __float_as_uint(p1.x) & 0xFFFF0000u;
    uint32_t h3 = __float_as_uint(p1.y) & 0xFFFF0000u;
    float l0 = p0.x - __uint_as_float(h0);
    float l1 = p0.y - __uint_as_float(h1);
    float l2 = p1.x - __uint_as_float(h2);
    float l3 = p1.y - __uint_as_float(h3);
    uint4 r;
    r.x = __byte_perm(h0, h1, 0x7632);
    asm("cvt.rn.bf16x2.f32 %0, %1, %2;" : "=r"(r.y) : "f"(l1), "f"(l0));
    r.z = __byte_perm(h2, h3, 0x7632);
    asm("cvt.rn.bf16x2.f32 %0, %1, %2;" : "=r"(r.w) : "f"(l3), "f"(l2));
    return r;
}

// m16n8k16 bf16 MMA: D(16x8,f32) += A(16x16) * B(16x8)
__device__ __forceinline__ void mma_bf16(float4& c,
                                         uint32_t a0, uint32_t a1, uint32_t a2, uint32_t a3,
                                         uint32_t b0, uint32_t b1) {
    asm volatile(
        "mma.sync.aligned.m16n8k16.row.col.f32.bf16.bf16.f32 "
        "{%0,%1,%2,%3}, {%4,%5,%6,%7}, {%8,%9}, {%0,%1,%2,%3};"
        : "+f"(c.x), "+f"(c.y), "+f"(c.z), "+f"(c.w)
        : "r"(a0), "r"(a1), "r"(a2), "r"(a3), "r"(b0), "r"(b1));
}

// ---------------------------------------------------------------------------
// bf16 3-term tensor-core GEMM + bias (AhBh + AlBh + AhBl; err ~2^-16)
// Triple-set: blockIdx.y selects (A, W, bias, C, ncols) so independent GEMMs
// share one launch (better wave packing, single launch tail).
// Block tile 128x64, 8 warps = 4(M) x 2(N), warp tile 32x32, K chunk 32.
// Register-pipelined staging: LDG for chunk kb+1 issued before chunk kb's MMAs.
// ---------------------------------------------------------------------------
__global__ void __launch_bounds__(256)
gemm_bf16(const float* __restrict__ A0, const float* __restrict__ W0,
          const float* __restrict__ b0, float* __restrict__ C0, int nc0, int yt0,
          const float* __restrict__ A1, const float* __restrict__ W1,
          const float* __restrict__ b1, float* __restrict__ C1, int nc1, int yt1,
          const float* __restrict__ A2, const float* __restrict__ W2,
          const float* __restrict__ b2, float* __restrict__ C2, int nc2,
          int rows)
{
    __shared__ uint4 As4[128 * 12];   // 24576 B
    __shared__ uint4 Bs4[64 * 12];    // 12288 B

    const int y = blockIdx.y;
    const float *A, *Wm, *bias;  float* C;  int ncols, colBase;
    if (y < yt0) {
        A = A0; Wm = W0; bias = b0; C = C0; ncols = nc0; colBase = y * 64;
    } else if (y < yt0 + yt1) {
        A = A1; Wm = W1; bias = b1; C = C1; ncols = nc1; colBase = (y - yt0) * 64;
    } else {
        A = A2; Wm = W2; bias = b2; C = C2; ncols = nc2; colBase = (y - yt0 - yt1) * 64;
    }

    const int tid  = threadIdx.x;
    const int lane = tid & 31;
    const int wid  = tid >> 5;
    const int wm   = wid & 3;
    const int wn   = wid >> 2;
    const int r    = lane >> 2;
    const int tig  = lane & 3;
    const int rowBase = blockIdx.x * 128;

    // staging decode (constant per thread)
    const int a_row = tid >> 3;              // 0..31 (+64*it)
    const int a_s   = (tid >> 2) & 1;
    const int a_t   = tid & 3;
    const int b_n   = tid & 63;
    const int b_st  = tid >> 6;              // 0..3 (+4*it)

    float4 acc[2][4];
    #pragma unroll
    for (int mt = 0; mt < 2; mt++)
        #pragma unroll
        for (int nt = 0; nt < 4; nt++)
            acc[mt][nt] = make_float4(0.f, 0.f, 0.f, 0.f);

    float2 aP0[4], aP1[4], bQ0[2], bQ1[2];

    // ---- register-pipelined chunk loader ----
#define LOAD_CHUNK(KB)                                                        \
    do {                                                                      \
        const int _k0 = (KB) * 32;                                            \
        _Pragma("unroll")                                                     \
        for (int it = 0; it < 4; it++) {                                      \
            int row  = a_row + it * 32;                                       \
            int grow = rowBase + row;                                         \
            if (grow < rows) {                                                \
                const float* ap = A + (size_t)grow * 256 + _k0 + a_s * 16 + 2 * a_t; \
                aP0[it] = *(const float2*)ap;                                 \
                aP1[it] = *(const float2*)(ap + 8);                           \
            } else {                                                          \
                aP0[it] = make_float2(0.f, 0.f);                              \
                aP1[it] = make_float2(0.f, 0.f);                              \
            }                                                                 \
        }                                                                     \
        _Pragma("unroll")                                                     \
        for (int it = 0; it < 2; it++) {                                      \
            int st = b_st + it * 4;                                           \
            int s  = st >> 2, t = st & 3;                                     \
            const float* wp = Wm + (size_t)(_k0 + s * 16 + 2 * t) * ncols + colBase + b_n; \
            bQ0[it] = make_float2(wp[0], wp[ncols]);                          \
            bQ1[it] = make_float2(wp[8 * ncols], wp[9 * ncols]);              \
        }                                                                     \
    } while (0)

    LOAD_CHUNK(0);

    for (int kb = 0; kb < 8; kb++) {
        // ---- convert + store staged registers to smem ----
        #pragma unroll
        for (int it = 0; it < 4; it++)
            As4[(a_row + it * 32) * 12 + a_s * 4 + a_t] = split_pack(aP0[it], aP1[it]);
        #pragma unroll
        for (int it = 0; it < 2; it++) {
            int st = b_st + it * 4;
            Bs4[b_n * 12 + st] = split_pack(bQ0[it], bQ1[it]);
        }
        __syncthreads();

        // ---- issue next chunk's global loads (overlap with MMAs) ----
        if (kb < 7) LOAD_CHUNK(kb + 1);

        // ---- compute: 2 ksteps of m16n8k16, 3-term split ----
        #pragma unroll
        for (int s = 0; s < 2; s++) {
            uint4 aw[2][2];
            #pragma unroll
            for (int mt = 0; mt < 2; mt++) {
                const int ar = wm * 32 + mt * 16 + r;
                aw[mt][0] = As4[ar * 12 + s * 4 + tig];
                aw[mt][1] = As4[(ar + 8) * 12 + s * 4 + tig];
            }
            #pragma unroll
            for (int nt = 0; nt < 4; nt++) {
                uint4 bw = Bs4[(wn * 32 + nt * 8 + r) * 12 + s * 4 + tig];
                #pragma unroll
                for (int mt = 0; mt < 2; mt++) {
                    mma_bf16(acc[mt][nt], aw[mt][0].x, aw[mt][1].x, aw[mt][0].z, aw[mt][1].z, bw.x, bw.z);
                    mma_bf16(acc[mt][nt], aw[mt][0].y, aw[mt][1].y, aw[mt][0].w, aw[mt][1].w, bw.x, bw.z);
                    mma_bf16(acc[mt][nt], aw[mt][0].x, aw[mt][1].x, aw[mt][0].z, aw[mt][1].z, bw.y, bw.w);
                }
            }
        }
        __syncthreads();
    }
#undef LOAD_CHUNK

    // ---- epilogue: +bias, float2 stores ----
    #pragma unroll
    for (int nt = 0; nt < 4; nt++) {
        const int col = colBase + wn * 32 + nt * 8 + tig * 2;
        const float bb0 = bias[col], bb1 = bias[col + 1];
        #pragma unroll
        for (int mt = 0; mt < 2; mt++) {
            const int row0 = rowBase + wm * 32 + mt * 16 + r;
            const float4 c4 = acc[mt][nt];
            if (row0 < rows)
                *(float2*)(C + (size_t)row0 * ncols + col) =
                    make_float2(c4.x + bb0, c4.y + bb1);
            if (row0 + 8 < rows)
                *(float2*)(C + (size_t)(row0 + 8) * ncols + col) =
                    make_float2(c4.z + bb0, c4.w + bb1);
        }
    }
}

// ---------------------------------------------------------------------------
// Fused softmax + deformable bilinear sampling (R9 version, ~85us)
// ---------------------------------------------------------------------------
__global__ void __launch_bounds__(256)
sample_kernel(const float* __restrict__ value,
              const float* __restrict__ offs,
              const float* __restrict__ alog,
              const float* __restrict__ refp,
              float* __restrict__ msout)
{
    __shared__ int4   sIdx[8][16];
    __shared__ float4 sWt [8][16];

    const int wid  = threadIdx.x >> 5;
    const int lane = threadIdx.x & 31;
    const int m    = wid;
    const int row  = blockIdx.x;
    const int b    = (row >= LQ) ? 1 : 0;

    const float* lg = alog + (size_t)row * 128 + m * 16;
    float v = (lane < 16) ? lg[lane] : -1e30f;
    float mx = v;
    #pragma unroll
    for (int o = 16; o; o >>= 1) mx = fmaxf(mx, __shfl_xor_sync(0xffffffffu, mx, o));
    float e = (lane < 16) ? expf(v - mx) : 0.f;
    float s = e;
    #pragma unroll
    for (int o = 16; o; o >>= 1) s += __shfl_xor_sync(0xffffffffu, s, o);
    const float inv = 1.f / s;

    if (lane < 16) {
        const int l  = lane >> 2;
        const int H  = c_H[l];
        const int W  = c_W[l];
        const int st = c_ST[l];
        const float fW = (float)W, fH = (float)H;

        const float rx = refp[(row * 4 + l) * 2 + 0];
        const float ry = refp[(row * 4 + l) * 2 + 1];
        const float* od = offs + (size_t)row * 256 + m * 32 + lane * 2;
        const float ox = od[0], oy = od[1];

        const float x = fmaf(rx, fW, ox) - 0.5f;
        const float y = fmaf(ry, fH, oy) - 0.5f;

        const float x0f = floorf(x), y0f = floorf(y);
        const float fx = x - x0f, fy = y - y0f;
        const int ix = (int)x0f, iy = (int)y0f;

        const float lw = e * inv;
        float w00 = (1.f - fx) * (1.f - fy) * lw;
        float w01 = fx * (1.f - fy) * lw;
        float w10 = (1.f - fx) * fy * lw;
        float w11 = fx * fy * lw;

        const bool vx0 = (ix >= 0) && (ix < W);
        const bool vx1 = (ix + 1 >= 0) && (ix + 1 < W);
        const bool vy0 = (iy >= 0) && (iy < H);
        const bool vy1 = (iy + 1 >= 0) && (iy + 1 < H);
        if (!(vx0 && vy0)) w00 = 0.f;
        if (!(vx1 && vy0)) w01 = 0.f;
        if (!(vx0 && vy1)) w10 = 0.f;
        if (!(vx1 && vy1)) w11 = 0.f;

        const int cx0 = min(max(ix, 0), W - 1);
        const int cx1 = min(max(ix + 1, 0), W - 1);
        const int cy0 = min(max(iy, 0), H - 1);
        const int cy1 = min(max(iy + 1, 0), H - 1);
        const int r0 = st + cy0 * W;
        const int r1 = st + cy1 * W;

        sIdx[wid][lane] = make_int4((r0 + cx0) * 256, (r0 + cx1) * 256,
                                    (r1 + cx0) * 256, (r1 + cx1) * 256);
        sWt [wid][lane] = make_float4(w00, w01, w10, w11);
    }
    __syncwarp();

    const int g  = lane >> 3;
    const int c4 = (lane & 7) * 4;
    const float* vb4 = value + (size_t)b * LQ * 256 + m * 32 + c4;

    float4 acc = make_float4(0.f, 0.f, 0.f, 0.f);
    #pragma unroll
    for (int pp = 0; pp < 4; pp++) {
        const int p = g * 4 + pp;
        const int4   I  = sIdx[wid][p];
        const float4 Wt = sWt[wid][p];
        float4 s0 = *(const float4*)(vb4 + I.x);
        float4 s1 = *(const float4*)(vb4 + I.y);
        float4 s2 = *(const float4*)(vb4 + I.z);
        float4 s3 = *(const float4*)(vb4 + I.w);
        acc.x = fmaf(Wt.x, s0.x, fmaf(Wt.y, s1.x, fmaf(Wt.z, s2.x, fmaf(Wt.w, s3.x, acc.x))));
        acc.y = fmaf(Wt.x, s0.y, fmaf(Wt.y, s1.y, fmaf(Wt.z, s2.y, fmaf(Wt.w, s3.y, acc.y))));
        acc.z = fmaf(Wt.x, s0.z, fmaf(Wt.y, s1.z, fmaf(Wt.z, s2.z, fmaf(Wt.w, s3.z, acc.z))));
        acc.w = fmaf(Wt.x, s0.w, fmaf(Wt.y, s1.w, fmaf(Wt.z, s2.w, fmaf(Wt.w, s3.w, acc.w))));
    }

    #pragma unroll
    for (int o = 8; o <= 16; o <<= 1) {
        acc.x += __shfl_xor_sync(0xffffffffu, acc.x, o);
        acc.y += __shfl_xor_sync(0xffffffffu, acc.y, o);
        acc.z += __shfl_xor_sync(0xffffffffu, acc.z, o);
        acc.w += __shfl_xor_sync(0xffffffffu, acc.w, o);
    }

    if (lane < 8)
        *(float4*)(msout + (size_t)row * 256 + m * 32 + c4) = acc;
}

// ---------------------------------------------------------------------------
// Launch: 3 graph-capturable kernel launches.
// ---------------------------------------------------------------------------
extern "C" void kernel_launch(void* const* d_in, const int* in_sizes, int n_in,
                              void* d_out, int out_size)
{
    (void)in_sizes; (void)n_in; (void)out_size;

    const float* query = (const float*)d_in[0];
    const float* refp  = (const float*)d_in[1];
    const float* inpf  = (const float*)d_in[2];
    const float* Wv = (const float*)d_in[4];
    const float* bv = (const float*)d_in[5];
    const float* Ws = (const float*)d_in[6];
    const float* bs = (const float*)d_in[7];
    const float* Wa = (const float*)d_in[8];
    const float* ba = (const float*)d_in[9];
    const float* Wo = (const float*)d_in[10];
    const float* bo = (const float*)d_in[11];
    float* out = (float*)d_out;

    float *value, *offs, *alog, *msout;
    cudaGetSymbolAddress((void**)&value, g_value);
    cudaGetSymbolAddress((void**)&offs,  g_offs);
    cudaGetSymbolAddress((void**)&alog,  g_alog);
    cudaGetSymbolAddress((void**)&msout, g_msout);

    const dim3 blk(256);
    const int  mTiles = (ROWS + 127) / 128;        // 192

    // 1) value / offs / alog in ONE launch (y = 4 + 4 + 2 = 10)
    gemm_bf16<<<dim3(mTiles, 10), blk>>>(
        inpf,  Wv, bv, value, 256, 4,
        query, Ws, bs, offs,  256, 4,
        query, Wa, ba, alog,  128,
        ROWS);
    // 2) fused softmax + deformable bilinear sampling
    sample_kernel<<<ROWS, blk>>>(value, offs, alog, refp, msout);
    // 3) out = msout @ Wo + bo
    gemm_bf16<<<dim3(mTiles, 4), blk>>>(
        msout, Wo, bo, out, 256, 4,
        msout, Wo, bo, out, 256, 0,
        msout, Wo, bo, out, 256,
        ROWS);
}

// round 11
// speedup vs baseline: 2.7956x; 1.0759x over previous
#include <cuda_runtime.h>
#include <cuda_bf16.h>
#include <math.h>
#include <stdint.h>

// ---------------------------------------------------------------------------
// Problem constants
// ---------------------------------------------------------------------------
#define BB   2
#define LQ   12240
#define DMO  256
#define MH   8
#define ROWS (BB * LQ)     // 24480

__device__ __constant__ int c_H[4]  = {96, 48, 24, 12};
__device__ __constant__ int c_W[4]  = {96, 48, 24, 12};
__device__ __constant__ int c_ST[4] = {0, 9216, 11520, 12096};

// ---------------------------------------------------------------------------
// Scratch (static device globals: allocation-free, graph-safe)
// ---------------------------------------------------------------------------
__device__ float g_value[ROWS * DMO];
__device__ float g_offs [ROWS * DMO];
__device__ float g_alog [ROWS * 128];
__device__ float g_msout[ROWS * DMO];

// pre-split bf16 fragment-layout buffers (uint4 slots)
__device__ uint4 g_inpf_sp [ROWS * 64];
__device__ uint4 g_query_sp[ROWS * 64];
__device__ uint4 g_msout_sp[ROWS * 64];
__device__ uint4 g_Wv_sp[64 * 256];
__device__ uint4 g_Ws_sp[64 * 256];
__device__ uint4 g_Wa_sp[64 * 128];
__device__ uint4 g_Wo_sp[64 * 256];

// ---------------------------------------------------------------------------
// bf16 split: hi = truncate-to-bf16 (exact residual), lo = rn(a-hi).
// Slot = {P0h, P0l, P1h, P1l}; P0 = k{2t,2t+1}, P1 = k{8+2t,8+2t+1},
// packed bf16x2 with even-k element in the LOW half.
// ---------------------------------------------------------------------------
__device__ __forceinline__ uint4 split_pack(float2 p0, float2 p1) {
    uint32_t h0 = __float_as_uint(p0.x) & 0xFFFF0000u;
    uint32_t h1 = __float_as_uint(p0.y) & 0xFFFF0000u;
    uint32_t h2 = __float_as_uint(p1.x) & 0xFFFF0000u;
    uint32_t h3 = __float_as_uint(p1.y) & 0xFFFF0000u;
    float l0 = p0.x - __uint_as_float(h0);
    float l1 = p0.y - __uint_as_float(h1);
    float l2 = p1.x - __uint_as_float(h2);
    float l3 = p1.y - __uint_as_float(h3);
    uint4 r;
    r.x = __byte_perm(h0, h1, 0x7632);
    asm("cvt.rn.bf16x2.f32 %0, %1, %2;" : "=r"(r.y) : "f"(l1), "f"(l0));
    r.z = __byte_perm(h2, h3, 0x7632);
    asm("cvt.rn.bf16x2.f32 %0, %1, %2;" : "=r"(r.w) : "f"(l3), "f"(l2));
    return r;
}

__device__ __forceinline__ void mma_bf16(float4& c,
                                         uint32_t a0, uint32_t a1, uint32_t a2, uint32_t a3,
                                         uint32_t b0, uint32_t b1) {
    asm volatile(
        "mma.sync.aligned.m16n8k16.row.col.f32.bf16.bf16.f32 "
        "{%0,%1,%2,%3}, {%4,%5,%6,%7}, {%8,%9}, {%0,%1,%2,%3};"
        : "+f"(c.x), "+f"(c.y), "+f"(c.z), "+f"(c.w)
        : "r"(a0), "r"(a1), "r"(a2), "r"(a3), "r"(b0), "r"(b1));
}

__device__ __forceinline__ uint32_t smem_u32(const void* p) {
    uint32_t a;
    asm("{ .reg .u64 t; cvta.to.shared.u64 t, %1; cvt.u32.u64 %0, t; }"
        : "=r"(a) : "l"(p));
    return a;
}

__device__ __forceinline__ void cp16(uint32_t smem, const void* gmem, uint32_t sz) {
    asm volatile("cp.async.cg.shared.global [%0], [%1], 16, %2;"
                 :: "r"(smem), "l"(gmem), "r"(sz) : "memory");
}
#define CP_COMMIT() asm volatile("cp.async.commit_group;" ::: "memory")
#define CP_WAIT(n)  asm volatile("cp.async.wait_group %0;" :: "n"(n) : "memory")

// ---------------------------------------------------------------------------
// Pre-convert A-style matrices [rows x 256] f32 -> fragment-layout uint4:
// dst[row*64 + chunk*8 + (s*4+t)] = split of k = chunk*32 + s*16 + 2t +{0,1,8,9}
// blockIdx.y selects (A0,D0) or (A1,D1).
// ---------------------------------------------------------------------------
__global__ void __launch_bounds__(256)
convert_A2(const float* __restrict__ A0, uint4* __restrict__ D0,
           const float* __restrict__ A1, uint4* __restrict__ D1, int rows)
{
    const float* src = blockIdx.y ? A1 : A0;
    uint4*       dst = blockIdx.y ? D1 : D0;
    int g = blockIdx.x * 256 + threadIdx.x;
    if (g >= rows * 64) return;
    int row  = g >> 6;
    int rest = g & 63;
    int chunk = rest >> 3;
    int s = (rest >> 2) & 1;
    int t = rest & 3;
    const float* p = src + (size_t)row * 256 + chunk * 32 + s * 16 + 2 * t;
    float2 p0 = *(const float2*)p;
    float2 p1 = *(const float2*)(p + 8);
    dst[g] = split_pack(p0, p1);
}

// ---------------------------------------------------------------------------
// Pre-convert weights [256 x ncols] f32 -> B fragment layout:
// dst[(chunk*ncols + n)*8 + s*4 + t] = split of W[k..][n] pairs along k.
// blockIdx.y selects one of 4 weight matrices.
// ---------------------------------------------------------------------------
__global__ void __launch_bounds__(256)
convert_W4(const float* __restrict__ W0, uint4* __restrict__ D0, int n0,
           const float* __restrict__ W1, uint4* __restrict__ D1, int n1,
           const float* __restrict__ W2, uint4* __restrict__ D2, int n2,
           const float* __restrict__ W3, uint4* __restrict__ D3, int n3)
{
    const float* Wm; uint4* D; int ncols;
    switch (blockIdx.y) {
        case 0:  Wm = W0; D = D0; ncols = n0; break;
        case 1:  Wm = W1; D = D1; ncols = n1; break;
        case 2:  Wm = W2; D = D2; ncols = n2; break;
        default: Wm = W3; D = D3; ncols = n3; break;
    }
    int g = blockIdx.x * 256 + threadIdx.x;
    if (g >= 64 * ncols) return;
    int n    = g % ncols;
    int rest = g / ncols;            // 0..63
    int chunk = rest >> 3;
    int s = (rest >> 2) & 1;
    int t = rest & 3;
    int k = chunk * 32 + s * 16 + 2 * t;
    const float* p = Wm + (size_t)k * ncols + n;
    float2 p0 = make_float2(p[0], p[ncols]);
    float2 p1 = make_float2(p[8 * ncols], p[9 * ncols]);
    D[(size_t)(chunk * ncols + n) * 8 + s * 4 + t] = split_pack(p0, p1);
}

// ---------------------------------------------------------------------------
// Pre-split bf16 3-term GEMM + bias. Pure data-mover mainloop:
// cp.async 16B gmem->smem (double-buffered), LDS.128 fragments, HMMA.
// Triple-set y-dispatch as before. Block 128x64, 8 warps 4x2, K chunk 32.
// smem per stage: A 128x12 uint4 (rows padded stride 12) + B 64x12 = 36864B.
// ---------------------------------------------------------------------------
#define STAGE_U4   2304            // 1536 (A) + 768 (B)
#define GEMM_SMEM  (2 * STAGE_U4 * 16)   // 73728 B

__global__ void __launch_bounds__(256, 3)
gemm_split(const uint4* __restrict__ A0, const uint4* __restrict__ P0,
           const float* __restrict__ b0, float* __restrict__ C0, int nc0, int yt0,
           const uint4* __restrict__ A1, const uint4* __restrict__ P1,
           const float* __restrict__ b1, float* __restrict__ C1, int nc1, int yt1,
           const uint4* __restrict__ A2, const uint4* __restrict__ P2,
           const float* __restrict__ b2, float* __restrict__ C2, int nc2,
           int rows)
{
    extern __shared__ uint4 sm[];

    const int y = blockIdx.y;
    const uint4 *Asp, *Wsp;  const float* bias;  float* C;  int ncols, colBase;
    if (y < yt0) {
        Asp = A0; Wsp = P0; bias = b0; C = C0; ncols = nc0; colBase = y * 64;
    } else if (y < yt0 + yt1) {
        Asp = A1; Wsp = P1; bias = b1; C = C1; ncols = nc1; colBase = (y - yt0) * 64;
    } else {
        Asp = A2; Wsp = P2; bias = b2; C = C2; ncols = nc2; colBase = (y - yt0 - yt1) * 64;
    }

    const int tid  = threadIdx.x;
    const int lane = tid & 31;
    const int wid  = tid >> 5;
    const int wm   = wid & 3;
    const int wn   = wid >> 2;
    const int r    = lane >> 2;
    const int tig  = lane & 3;
    const int rowBase = blockIdx.x * 128;

    const uint32_t smem_base = smem_u32(sm);
    const int a_row  = tid >> 3;       // 0..31 (+32*it)
    const int a_slot = tid & 7;

    float4 acc[2][4];
    #pragma unroll
    for (int mt = 0; mt < 2; mt++)
        #pragma unroll
        for (int nt = 0; nt < 4; nt++)
            acc[mt][nt] = make_float4(0.f, 0.f, 0.f, 0.f);

#define LOAD_CHUNK(KB, ST)                                                    \
    do {                                                                      \
        const uint32_t _base = smem_base + (ST) * (STAGE_U4 * 16);            \
        _Pragma("unroll")                                                     \
        for (int it = 0; it < 4; it++) {                                      \
            int row  = a_row + it * 32;                                       \
            int grow = rowBase + row;                                         \
            cp16(_base + (uint32_t)(row * 12 + a_slot) * 16,                  \
                 Asp + ((size_t)grow * 64 + (KB) * 8 + a_slot),               \
                 (grow < rows) ? 16u : 0u);                                   \
        }                                                                     \
        _Pragma("unroll")                                                     \
        for (int it = 0; it < 2; it++) {                                      \
            int n = a_row + it * 32;                                          \
            if (n < 64)                                                       \
                cp16(_base + (uint32_t)(1536 + n * 12 + a_slot) * 16,         \
                     Wsp + ((size_t)((KB) * ncols + colBase + n) * 8 + a_slot), 16u); \
        }                                                                     \
        CP_COMMIT();                                                          \
    } while (0)

    LOAD_CHUNK(0, 0);

    for (int kb = 0; kb < 8; kb++) {
        if (kb < 7) {
            LOAD_CHUNK(kb + 1, (kb + 1) & 1);
            CP_WAIT(1);
        } else {
            CP_WAIT(0);
        }
        __syncthreads();

        const uint4* As4 = sm + (kb & 1) * STAGE_U4;
        const uint4* Bs4 = As4 + 1536;

        #pragma unroll
        for (int s = 0; s < 2; s++) {
            uint4 aw[2][2];
            #pragma unroll
            for (int mt = 0; mt < 2; mt++) {
                const int ar = wm * 32 + mt * 16 + r;
                aw[mt][0] = As4[ar * 12 + s * 4 + tig];
                aw[mt][1] = As4[(ar + 8) * 12 + s * 4 + tig];
            }
            #pragma unroll
            for (int nt = 0; nt < 4; nt++) {
                uint4 bw = Bs4[(wn * 32 + nt * 8 + r) * 12 + s * 4 + tig];
                #pragma unroll
                for (int mt = 0; mt < 2; mt++) {
                    mma_bf16(acc[mt][nt], aw[mt][0].x, aw[mt][1].x, aw[mt][0].z, aw[mt][1].z, bw.x, bw.z);
                    mma_bf16(acc[mt][nt], aw[mt][0].y, aw[mt][1].y, aw[mt][0].w, aw[mt][1].w, bw.x, bw.z);
                    mma_bf16(acc[mt][nt], aw[mt][0].x, aw[mt][1].x, aw[mt][0].z, aw[mt][1].z, bw.y, bw.w);
                }
            }
        }
        __syncthreads();
    }
#undef LOAD_CHUNK

    // ---- epilogue: +bias, float2 stores ----
    #pragma unroll
    for (int nt = 0; nt < 4; nt++) {
        const int col = colBase + wn * 32 + nt * 8 + tig * 2;
        const float bb0 = bias[col], bb1 = bias[col + 1];
        #pragma unroll
        for (int mt = 0; mt < 2; mt++) {
            const int row0 = rowBase + wm * 32 + mt * 16 + r;
            const float4 c4 = acc[mt][nt];
            if (row0 < rows)
                *(float2*)(C + (size_t)row0 * ncols + col) =
                    make_float2(c4.x + bb0, c4.y + bb1);
            if (row0 + 8 < rows)
                *(float2*)(C + (size_t)(row0 + 8) * ncols + col) =
                    make_float2(c4.z + bb0, c4.w + bb1);
        }
    }
}

// ---------------------------------------------------------------------------
// Fused softmax + deformable bilinear sampling (R9/R10 version)
// ---------------------------------------------------------------------------
__global__ void __launch_bounds__(256)
sample_kernel(const float* __restrict__ value,
              const float* __restrict__ offs,
              const float* __restrict__ alog,
              const float* __restrict__ refp,
              float* __restrict__ msout)
{
    __shared__ int4   sIdx[8][16];
    __shared__ float4 sWt [8][16];

    const int wid  = threadIdx.x >> 5;
    const int lane = threadIdx.x & 31;
    const int m    = wid;
    const int row  = blockIdx.x;
    const int b    = (row >= LQ) ? 1 : 0;

    const float* lg = alog + (size_t)row * 128 + m * 16;
    float v = (lane < 16) ? lg[lane] : -1e30f;
    float mx = v;
    #pragma unroll
    for (int o = 16; o; o >>= 1) mx = fmaxf(mx, __shfl_xor_sync(0xffffffffu, mx, o));
    float e = (lane < 16) ? expf(v - mx) : 0.f;
    float s = e;
    #pragma unroll
    for (int o = 16; o; o >>= 1) s += __shfl_xor_sync(0xffffffffu, s, o);
    const float inv = 1.f / s;

    if (lane < 16) {
        const int l  = lane >> 2;
        const int H  = c_H[l];
        const int W  = c_W[l];
        const int st = c_ST[l];
        const float fW = (float)W, fH = (float)H;

        const float rx = refp[(row * 4 + l) * 2 + 0];
        const float ry = refp[(row * 4 + l) * 2 + 1];
        const float* od = offs + (size_t)row * 256 + m * 32 + lane * 2;
        const float ox = od[0], oy = od[1];

        const float x = fmaf(rx, fW, ox) - 0.5f;
        const float y = fmaf(ry, fH, oy) - 0.5f;

        const float x0f = floorf(x), y0f = floorf(y);
        const float fx = x - x0f, fy = y - y0f;
        const int ix = (int)x0f, iy = (int)y0f;

        const float lw = e * inv;
        float w00 = (1.f - fx) * (1.f - fy) * lw;
        float w01 = fx * (1.f - fy) * lw;
        float w10 = (1.f - fx) * fy * lw;
        float w11 = fx * fy * lw;

        const bool vx0 = (ix >= 0) && (ix < W);
        const bool vx1 = (ix + 1 >= 0) && (ix + 1 < W);
        const bool vy0 = (iy >= 0) && (iy < H);
        const bool vy1 = (iy + 1 >= 0) && (iy + 1 < H);
        if (!(vx0 && vy0)) w00 = 0.f;
        if (!(vx1 && vy0)) w01 = 0.f;
        if (!(vx0 && vy1)) w10 = 0.f;
        if (!(vx1 && vy1)) w11 = 0.f;

        const int cx0 = min(max(ix, 0), W - 1);
        const int cx1 = min(max(ix + 1, 0), W - 1);
        const int cy0 = min(max(iy, 0), H - 1);
        const int cy1 = min(max(iy + 1, 0), H - 1);
        const int r0 = st + cy0 * W;
        const int r1 = st + cy1 * W;

        sIdx[wid][lane] = make_int4((r0 + cx0) * 256, (r0 + cx1) * 256,
                                    (r1 + cx0) * 256, (r1 + cx1) * 256);
        sWt [wid][lane] = make_float4(w00, w01, w10, w11);
    }
    __syncwarp();

    const int g  = lane >> 3;
    const int c4 = (lane & 7) * 4;
    const float* vb4 = value + (size_t)b * LQ * 256 + m * 32 + c4;

    float4 acc = make_float4(0.f, 0.f, 0.f, 0.f);
    #pragma unroll
    for (int pp = 0; pp < 4; pp++) {
        const int p = g * 4 + pp;
        const int4   I  = sIdx[wid][p];
        const float4 Wt = sWt[wid][p];
        float4 s0 = *(const float4*)(vb4 + I.x);
        float4 s1 = *(const float4*)(vb4 + I.y);
        float4 s2 = *(const float4*)(vb4 + I.z);
        float4 s3 = *(const float4*)(vb4 + I.w);
        acc.x = fmaf(Wt.x, s0.x, fmaf(Wt.y, s1.x, fmaf(Wt.z, s2.x, fmaf(Wt.w, s3.x, acc.x))));
        acc.y = fmaf(Wt.x, s0.y, fmaf(Wt.y, s1.y, fmaf(Wt.z, s2.y, fmaf(Wt.w, s3.y, acc.y))));
        acc.z = fmaf(Wt.x, s0.z, fmaf(Wt.y, s1.z, fmaf(Wt.z, s2.z, fmaf(Wt.w, s3.z, acc.z))));
        acc.w = fmaf(Wt.x, s0.w, fmaf(Wt.y, s1.w, fmaf(Wt.z, s2.w, fmaf(Wt.w, s3.w, acc.w))));
    }

    #pragma unroll
    for (int o = 8; o <= 16; o <<= 1) {
        acc.x += __shfl_xor_sync(0xffffffffu, acc.x, o);
        acc.y += __shfl_xor_sync(0xffffffffu, acc.y, o);
        acc.z += __shfl_xor_sync(0xffffffffu, acc.z, o);
        acc.w += __shfl_xor_sync(0xffffffffu, acc.w, o);
    }

    if (lane < 8)
        *(float4*)(msout + (size_t)row * 256 + m * 32 + c4) = acc;
}

// ---------------------------------------------------------------------------
// Launch: 6 graph-capturable kernel launches.
// ---------------------------------------------------------------------------
extern "C" void kernel_launch(void* const* d_in, const int* in_sizes, int n_in,
                              void* d_out, int out_size)
{
    (void)in_sizes; (void)n_in; (void)out_size;

    const float* query = (const float*)d_in[0];
    const float* refp  = (const float*)d_in[1];
    const float* inpf  = (const float*)d_in[2];
    const float* Wv = (const float*)d_in[4];
    const float* bv = (const float*)d_in[5];
    const float* Ws = (const float*)d_in[6];
    const float* bs = (const float*)d_in[7];
    const float* Wa = (const float*)d_in[8];
    const float* ba = (const float*)d_in[9];
    const float* Wo = (const float*)d_in[10];
    const float* bo = (const float*)d_in[11];
    float* out = (float*)d_out;

    float *value, *offs, *alog, *msout;
    uint4 *inpf_sp, *query_sp, *msout_sp, *Wv_sp, *Ws_sp, *Wa_sp, *Wo_sp;
    cudaGetSymbolAddress((void**)&value, g_value);
    cudaGetSymbolAddress((void**)&offs,  g_offs);
    cudaGetSymbolAddress((void**)&alog,  g_alog);
    cudaGetSymbolAddress((void**)&msout, g_msout);
    cudaGetSymbolAddress((void**)&inpf_sp,  g_inpf_sp);
    cudaGetSymbolAddress((void**)&query_sp, g_query_sp);
    cudaGetSymbolAddress((void**)&msout_sp, g_msout_sp);
    cudaGetSymbolAddress((void**)&Wv_sp, g_Wv_sp);
    cudaGetSymbolAddress((void**)&Ws_sp, g_Ws_sp);
    cudaGetSymbolAddress((void**)&Wa_sp, g_Wa_sp);
    cudaGetSymbolAddress((void**)&Wo_sp, g_Wo_sp);

    cudaFuncSetAttribute(gemm_split, cudaFuncAttributeMaxDynamicSharedMemorySize,
                         GEMM_SMEM);

    const dim3 blk(256);
    const int  mTiles = (ROWS + 127) / 128;        // 192
    const int  aBlocks = ROWS * 64 / 256;          // 6120

    // 1) weights -> split fragment layout (tiny)
    convert_W4<<<dim3(64, 4), blk>>>(Wv, Wv_sp, 256, Ws, Ws_sp, 256,
                                     Wa, Wa_sp, 128, Wo, Wo_sp, 256);
    // 2) inpf + query -> split fragment layout
    convert_A2<<<dim3(aBlocks, 2), blk>>>(inpf, inpf_sp, query, query_sp, ROWS);
    // 3) value / offs / alog in ONE launch (y = 4 + 4 + 2 = 10)
    gemm_split<<<dim3(mTiles, 10), blk, GEMM_SMEM>>>(
        inpf_sp,  Wv_sp, bv, value, 256, 4,
        query_sp, Ws_sp, bs, offs,  256, 4,
        query_sp, Wa_sp, ba, alog,  128,
        ROWS);
    // 4) fused softmax + deformable bilinear sampling
    sample_kernel<<<ROWS, blk>>>(value, offs, alog, refp, msout);
    // 5) msout -> split fragment layout
    convert_A2<<<dim3(aBlocks, 1), blk>>>(msout, msout_sp, msout, msout_sp, ROWS);
    // 6) out = msout @ Wo + bo
    gemm_split<<<dim3(mTiles, 4), blk, GEMM_SMEM>>>(
        msout_sp, Wo_sp, bo, out, 256, 4,
        msout_sp, Wo_sp, bo, out, 256, 0,
        msout_sp, Wo_sp, bo, out, 256,
        ROWS);
}